// round 2
// baseline (speedup 1.0000x reference)
#include <cuda_runtime.h>

#define NBLK 148
#define NTHR 256
#define LDS_ 132   // padded smem row stride (floats): 528B, 16B aligned, conflict-free float4

// Scratch (allocation-free rule: __device__ globals)
__device__ float g_w1t[512 * 128];   // W1^T: [c=512][n=128], W1 = fp_W @ gat_W^T
__device__ float g_b1[512];          // fp_b @ gat_W^T
__device__ float g_r[512 * 512];     // relu(x @ W1 + b1)
__device__ unsigned g_cnt = 0;       // barrier arrival counter (returns to 0 each launch)
__device__ unsigned g_gen = 0;       // barrier generation (monotonic across launches — fine)

__device__ __forceinline__ void grid_barrier()
{
    __threadfence();
    __syncthreads();
    if (threadIdx.x == 0) {
        unsigned gen = *(volatile unsigned*)&g_gen;   // read BEFORE arriving
        unsigned t = atomicAdd(&g_cnt, 1u);
        if (t == NBLK - 1) {
            g_cnt = 0;
            __threadfence();
            atomicAdd(&g_gen, 1u);                    // release
        } else {
            while (*(volatile unsigned*)&g_gen == gen) { }
        }
    }
    __syncthreads();
}

// C tile [32 x 64] = A[32 x (NK*128)] * B (+epilogue), K in 128-wide smem chunks.
// TRB=true : B given as 64 rows x 128 (dot-of-rows), NK must be 1.
// TRB=false: B is [NK*128 x ldB] row-major; take cols [bn0, bn0+64), transpose into smem.
// EPI: 0 plain store; 1 v+=bias[n], relu; 2 imputer epilogue (xt/mt tiles, ld 128, bias=op_b+p0).
template<int EPI, bool TRB, int NK>
__device__ __forceinline__ void gemm_tile(
    float* sm,
    const float* __restrict__ A, int ldA,
    const float* __restrict__ B, int ldB, int bn0,
    const float* __restrict__ bias,
    float* __restrict__ C, int ldC,
    const float* __restrict__ xt, const float* __restrict__ mt)
{
    float* As = sm;               // 32 x LDS_
    float* Bs = sm + 32 * LDS_;   // 64 x LDS_ (row = n_local, col = k)
    const int t = threadIdx.x;
    const int tx = t & 31, ty = t >> 5;   // n = tx + 32j, m = ty + 8i

    float acc[4][2];
    #pragma unroll
    for (int i = 0; i < 4; i++) { acc[i][0] = 0.f; acc[i][1] = 0.f; }

    #pragma unroll
    for (int z = 0; z < NK; z++) {
        const float* Az = A + z * 128;
        #pragma unroll
        for (int i = 0; i < 4; i++) {
            int idx = t + i * 256; int r = idx >> 5, c4 = idx & 31;
            *(float4*)(As + r * LDS_ + c4 * 4) =
                *(const float4*)(Az + (size_t)r * ldA + c4 * 4);
        }
        if (TRB) {
            #pragma unroll
            for (int i = 0; i < 8; i++) {
                int idx = t + i * 256; int r = idx >> 5, c4 = idx & 31;
                *(float4*)(Bs + r * LDS_ + c4 * 4) =
                    *(const float4*)(B + (size_t)r * ldB + c4 * 4);
            }
        } else {
            const float* Bz = B + (size_t)z * 128 * ldB;
            #pragma unroll
            for (int i = 0; i < 8; i++) {
                int idx = t + i * 256; int kk = idx >> 4, p4 = idx & 15;
                float4 v = *(const float4*)(Bz + (size_t)kk * ldB + bn0 + p4 * 4);
                Bs[(p4 * 4 + 0) * LDS_ + kk] = v.x;
                Bs[(p4 * 4 + 1) * LDS_ + kk] = v.y;
                Bs[(p4 * 4 + 2) * LDS_ + kk] = v.z;
                Bs[(p4 * 4 + 3) * LDS_ + kk] = v.w;
            }
        }
        __syncthreads();

        #pragma unroll 8
        for (int f4 = 0; f4 < 32; f4++) {
            float4 a[4], b[2];
            #pragma unroll
            for (int i = 0; i < 4; i++)
                a[i] = *(const float4*)(As + (ty + 8 * i) * LDS_ + f4 * 4);
            #pragma unroll
            for (int j = 0; j < 2; j++)
                b[j] = *(const float4*)(Bs + (tx + 32 * j) * LDS_ + f4 * 4);
            #pragma unroll
            for (int i = 0; i < 4; i++)
                #pragma unroll
                for (int j = 0; j < 2; j++) {
                    acc[i][j] += a[i].x * b[j].x;
                    acc[i][j] += a[i].y * b[j].y;
                    acc[i][j] += a[i].z * b[j].z;
                    acc[i][j] += a[i].w * b[j].w;
                }
        }
        if (z + 1 < NK) __syncthreads();
    }

    #pragma unroll
    for (int i = 0; i < 4; i++) {
        int m = ty + 8 * i;
        #pragma unroll
        for (int j = 0; j < 2; j++) {
            int n = tx + 32 * j;
            float v = acc[i][j];
            if (EPI == 1) v = fmaxf(v + bias[n], 0.f);
            if (EPI == 2) {
                v += bias[n];
                float xv = xt[(size_t)m * 128 + n];
                float mv = mt[(size_t)m * 128 + n];
                v = xv * (1.0f - mv) + v * mv;
            }
            C[(size_t)m * ldC + n] = v;
        }
    }
}

__global__ void __launch_bounds__(NTHR, 1)
fused_kernel(const float* __restrict__ x,   const float* __restrict__ mask,
             const float* __restrict__ emb, const float* __restrict__ gatW,
             const float* __restrict__ fpW, const float* __restrict__ fpb,
             const float* __restrict__ opW, const float* __restrict__ opb,
             const int*   __restrict__ kp,  float* __restrict__ out)
{
    extern __shared__ float sm[];
    const int blk = blockIdx.x, t = threadIdx.x;

    // ── Phase 0: adj (blk<64) ∥ W1^T tiles (64..95) ∥ b1 (96) ───────────────
    if (blk < 64) {
        // adjacency: rows 2*blk and 2*blk+1 (cosine-sim top-k, lower index wins ties)
        float* es    = sm;                  // 128 x LDS_
        float* s_n2  = sm + 128 * LDS_;     // 128
        float* s_sim = s_n2 + 128;          // 2 x 128
        #pragma unroll
        for (int i = 0; i < 16; i++) {
            int idx = t + i * 256; int r = idx >> 5, c4 = idx & 31;
            *(float4*)(es + r * LDS_ + c4 * 4) =
                *(const float4*)(emb + (size_t)r * 128 + c4 * 4);
        }
        __syncthreads();
        const int rr = t >> 7, j = t & 127;
        const int irow = blk * 2 + rr;
        const float* ei = es + irow * LDS_;
        const float* ej = es + j * LDS_;
        float dij = 0.f, njj = 0.f;
        #pragma unroll 8
        for (int f4 = 0; f4 < 32; f4++) {
            float4 a = *(const float4*)(ei + f4 * 4);
            float4 b = *(const float4*)(ej + f4 * 4);
            dij += a.x * b.x + a.y * b.y + a.z * b.z + a.w * b.w;
            njj += b.x * b.x + b.y * b.y + b.z * b.z + b.w * b.w;
        }
        if (rr == 0) s_n2[j] = njj;
        __syncthreads();
        float sim = dij / (sqrtf(s_n2[irow]) * sqrtf(s_n2[j]));
        s_sim[rr * 128 + j] = sim;
        __syncthreads();
        const float* srow = s_sim + rr * 128;
        int cnt = 0;
        #pragma unroll 8
        for (int jj = 0; jj < 128; jj++) {
            float s2 = srow[jj];
            cnt += (s2 > sim) || (s2 == sim && jj < j);
        }
        out[65536 + irow * 128 + j] = (cnt < kp[0]) ? 1.0f : 0.0f;
    } else if (blk < 96) {
        // W1^T[c, n] = sum_f gat_W[c, f] * fp_W[n, f]  (both K-major row dots)
        int tt = blk - 64;
        int c0 = (tt >> 1) * 32, n0 = (tt & 1) * 64;
        gemm_tile<0, true, 1>(sm, gatW + (size_t)c0 * 128, 128,
                              fpW + (size_t)n0 * 128, 128, 0, nullptr,
                              g_w1t + (size_t)c0 * 128 + n0, 128, nullptr, nullptr);
    } else if (blk == 96) {
        // b1[c] = fp_b . gat_W[c, :]
        for (int c = t; c < 512; c += 256) {
            float s = 0.f;
            #pragma unroll 8
            for (int f4 = 0; f4 < 32; f4++) {
                float4 a = *(const float4*)(fpb + f4 * 4);
                float4 b = *(const float4*)(gatW + (size_t)c * 128 + f4 * 4);
                s += a.x * b.x + a.y * b.y + a.z * b.z + a.w * b.w;
            }
            g_b1[c] = s;
        }
    }
    grid_barrier();

    // ── Phase 1: r = relu(x @ W1 + b1), 512x512, K=128 — 128 tiles ──────────
    if (blk < 128) {
        int m0 = (blk >> 3) * 32, c0 = (blk & 7) * 64;
        gemm_tile<1, true, 1>(sm, x + (size_t)m0 * 128, 128,
                              g_w1t + (size_t)c0 * 128, 128, 0, g_b1 + c0,
                              g_r + (size_t)m0 * 512 + c0, 512, nullptr, nullptr);
    }
    grid_barrier();

    // ── Phase 2: out = x(1-mask) + (r @ op_W + op_b) mask, K=512 — 32 tiles ─
    if (blk < 32) {
        int m0 = (blk >> 1) * 32, p0 = (blk & 1) * 64;
        gemm_tile<2, false, 4>(sm, g_r + (size_t)m0 * 512, 512,
                               opW, 128, p0, opb + p0,
                               out + (size_t)m0 * 128 + p0, 128,
                               x + (size_t)m0 * 128 + p0,
                               mask + (size_t)m0 * 128 + p0);
    }
}

extern "C" void kernel_launch(void* const* d_in, const int* in_sizes, int n_in,
                              void* d_out, int out_size)
{
    const float* x    = (const float*)d_in[0];
    const float* mask = (const float*)d_in[1];
    const float* emb  = (const float*)d_in[2];
    const float* gatW = (const float*)d_in[3];
    // d_in[4] = gat_a: provably unused (softmax over constant logits -> adj/k; rows sum to 1)
    const float* fpW  = (const float*)d_in[5];
    const float* fpb  = (const float*)d_in[6];
    const float* opW  = (const float*)d_in[7];
    const float* opb  = (const float*)d_in[8];
    const int*   kp   = (const int*)d_in[9];
    float* out = (float*)d_out;

    const int SMEM = (128 * LDS_ + 128 + 256) * 4;  // 69120 B (adj phase is the max)
    cudaFuncSetAttribute(fused_kernel, cudaFuncAttributeMaxDynamicSharedMemorySize, SMEM);
    fused_kernel<<<NBLK, NTHR, SMEM>>>(x, mask, emb, gatW, fpW, fpb, opW, opb, kp, out);
}

// round 3
// speedup vs baseline: 1.6044x; 1.6044x over previous
#include <cuda_runtime.h>

#define LDS_ 132   // padded smem row stride (floats): 528B = 16B-aligned, stride-132 float4 is bank-conflict-free
typedef unsigned long long u64;

// Scratch (allocation-free rule: __device__ globals)
__device__ float g_h0[512 * 128];   // x @ fp_W + fp_b
__device__ float g_r[512 * 512];    // relu(h0 @ gat_W^T)

__device__ __forceinline__ u64 ffma2(u64 a, u64 b, u64 c) {
    u64 d;
    asm("fma.rn.f32x2 %0, %1, %2, %3;" : "=l"(d) : "l"(a), "l"(b), "l"(c));
    return d;
}
__device__ __forceinline__ float f2lo(u64 v) { return __uint_as_float((unsigned)v); }
__device__ __forceinline__ float f2hi(u64 v) { return __uint_as_float((unsigned)(v >> 32)); }

// Warp-cooperative tile: this warp computes 8 m-rows (As rows mw0..mw0+7, broadcast
// loads) x 64 n-cols (n = lane + 32j, strided conflict-free loads) over one K=128 chunk.
// acc[i][j] accumulates packed f32x2 pairs (lo = even k, hi = odd k).
__device__ __forceinline__ void wtile(const float* __restrict__ As,
                                      const float* __restrict__ Bs,
                                      int mw0, int lane, u64 acc[8][2])
{
    #pragma unroll 4
    for (int k4 = 0; k4 < 32; k4++) {
        ulonglong2 b0 = *(const ulonglong2*)(Bs + (size_t)lane        * LDS_ + k4 * 4);
        ulonglong2 b1 = *(const ulonglong2*)(Bs + (size_t)(lane + 32) * LDS_ + k4 * 4);
        #pragma unroll
        for (int i = 0; i < 8; i++) {
            ulonglong2 a = *(const ulonglong2*)(As + (size_t)(mw0 + i) * LDS_ + k4 * 4);
            acc[i][0] = ffma2(a.x, b0.x, acc[i][0]);
            acc[i][0] = ffma2(a.y, b0.y, acc[i][0]);
            acc[i][1] = ffma2(a.x, b1.x, acc[i][1]);
            acc[i][1] = ffma2(a.y, b1.y, acc[i][1]);
        }
    }
}

// ── K1: blk<64 -> adjacency (2 rows per block); blk 64..95 -> h0 GEMM tiles ──
__global__ void __launch_bounds__(128, 1)
k1_kernel(const float* __restrict__ emb, const float* __restrict__ x,
          const float* __restrict__ fpW, const float* __restrict__ fpb,
          const int* __restrict__ kp, float* __restrict__ out)
{
    extern __shared__ float sm[];
    const int t = threadIdx.x, lane = t & 31, w = t >> 5;
    const int blk = blockIdx.x;

    if (blk < 64) {
        // cosine-sim top-k adjacency, rows 2*blk, 2*blk+1 (lower index wins ties)
        float* es    = sm;                 // 128 x LDS_
        float* s_n2  = sm + 128 * LDS_;    // 128
        float* s_sim = s_n2 + 128;         // 2 x 128
        #pragma unroll
        for (int i = 0; i < 32; i++) {
            int idx = t + i * 128; int r = idx >> 5, c4 = idx & 31;
            *(float4*)(es + r * LDS_ + c4 * 4) =
                *(const float4*)(emb + (size_t)r * 128 + c4 * 4);
        }
        __syncthreads();
        const int i0 = blk * 2, i1 = i0 + 1, j = t;
        const float* e0 = es + i0 * LDS_;
        const float* e1 = es + i1 * LDS_;
        const float* ej = es + j * LDS_;
        float d0 = 0.f, d1 = 0.f, nj = 0.f;
        #pragma unroll 8
        for (int f4 = 0; f4 < 32; f4++) {
            float4 b  = *(const float4*)(ej + f4 * 4);
            float4 a0 = *(const float4*)(e0 + f4 * 4);
            float4 a1 = *(const float4*)(e1 + f4 * 4);
            d0 += a0.x * b.x + a0.y * b.y + a0.z * b.z + a0.w * b.w;
            d1 += a1.x * b.x + a1.y * b.y + a1.z * b.z + a1.w * b.w;
            nj += b.x * b.x + b.y * b.y + b.z * b.z + b.w * b.w;
        }
        s_n2[j] = nj;
        __syncthreads();
        float sj = sqrtf(nj);
        float r0 = d0 / (sqrtf(s_n2[i0]) * sj);
        float r1 = d1 / (sqrtf(s_n2[i1]) * sj);
        s_sim[j] = r0; s_sim[128 + j] = r1;
        __syncthreads();
        int c0 = 0, c1 = 0;
        #pragma unroll 8
        for (int jj = 0; jj < 128; jj++) {
            float s0 = s_sim[jj], s1 = s_sim[128 + jj];
            c0 += (s0 > r0) || (s0 == r0 && jj < j);
            c1 += (s1 > r1) || (s1 == r1 && jj < j);
        }
        int k = kp[0];
        out[65536 + i0 * 128 + j] = (c0 < k) ? 1.0f : 0.0f;
        out[65536 + i1 * 128 + j] = (c1 < k) ? 1.0f : 0.0f;
    } else {
        // h0 tile [32 x 64]: h0 = x @ fp_W + fp_b, K=128
        int tt = blk - 64;
        int m0 = (tt >> 1) * 32, n0 = (tt & 1) * 64;
        float* As = sm;               // 32 x LDS_
        float* Bs = sm + 32 * LDS_;   // 64 x LDS_  (row = n_local, col = k)
        #pragma unroll
        for (int i = 0; i < 8; i++) {
            int idx = t + i * 128; int r = idx >> 5, c4 = idx & 31;
            *(float4*)(As + r * LDS_ + c4 * 4) =
                *(const float4*)(x + (size_t)(m0 + r) * 128 + c4 * 4);
        }
        // transpose fp_W cols [n0, n0+64): thread t owns k-row t -> STS conflict-free
        #pragma unroll
        for (int p4 = 0; p4 < 16; p4++) {
            float4 v = *(const float4*)(fpW + (size_t)t * 128 + n0 + p4 * 4);
            Bs[(p4 * 4 + 0) * LDS_ + t] = v.x;
            Bs[(p4 * 4 + 1) * LDS_ + t] = v.y;
            Bs[(p4 * 4 + 2) * LDS_ + t] = v.z;
            Bs[(p4 * 4 + 3) * LDS_ + t] = v.w;
        }
        __syncthreads();
        u64 acc[8][2];
        #pragma unroll
        for (int i = 0; i < 8; i++) { acc[i][0] = 0ull; acc[i][1] = 0ull; }
        wtile(As, Bs, w * 8, lane, acc);
        #pragma unroll
        for (int i = 0; i < 8; i++) {
            int m = m0 + w * 8 + i;
            #pragma unroll
            for (int j = 0; j < 2; j++) {
                int n = n0 + lane + 32 * j;
                g_h0[(size_t)m * 128 + n] = f2lo(acc[i][j]) + f2hi(acc[i][j]) + fpb[n];
            }
        }
    }
}

// ── K2: r = relu(h0 @ gat_W^T), 512x512, K=128; 128 tiles of [32 x 64] ──────
__global__ void __launch_bounds__(128, 1)
k2_kernel(const float* __restrict__ gatW)
{
    extern __shared__ float sm[];
    float* As = sm;               // 32 x LDS_
    float* Bs = sm + 32 * LDS_;   // 64 x LDS_
    const int t = threadIdx.x, lane = t & 31, w = t >> 5;
    const int m0 = (blockIdx.x >> 3) * 32, c0 = (blockIdx.x & 7) * 64;

    #pragma unroll
    for (int i = 0; i < 8; i++) {
        int idx = t + i * 128; int r = idx >> 5, c4 = idx & 31;
        *(float4*)(As + r * LDS_ + c4 * 4) =
            *(const float4*)(g_h0 + (size_t)(m0 + r) * 128 + c4 * 4);
    }
    // gat_W rows are already K-contiguous per output col c: direct copy
    #pragma unroll
    for (int i = 0; i < 16; i++) {
        int idx = t + i * 128; int r = idx >> 5, c4 = idx & 31;
        *(float4*)(Bs + r * LDS_ + c4 * 4) =
            *(const float4*)(gatW + (size_t)(c0 + r) * 128 + c4 * 4);
    }
    __syncthreads();
    u64 acc[8][2];
    #pragma unroll
    for (int i = 0; i < 8; i++) { acc[i][0] = 0ull; acc[i][1] = 0ull; }
    wtile(As, Bs, w * 8, lane, acc);
    #pragma unroll
    for (int i = 0; i < 8; i++) {
        int m = m0 + w * 8 + i;
        #pragma unroll
        for (int j = 0; j < 2; j++) {
            int c = c0 + lane + 32 * j;
            g_r[(size_t)m * 512 + c] = fmaxf(f2lo(acc[i][j]) + f2hi(acc[i][j]), 0.0f);
        }
    }
}

// ── K3: out = x(1-mask) + (r @ op_W + op_b)·mask, 512x128, K=512 ────────────
// 64 blocks, tile [16 x 64]. Warp-pairs split K: group g (warps 2g,2g+1) does
// K-chunks {2g, 2g+1}; group 1 spills to smem, group 0 reduces + epilogue.
__global__ void __launch_bounds__(128, 1)
k3_kernel(const float* __restrict__ x, const float* __restrict__ mask,
          const float* __restrict__ opW, const float* __restrict__ opb,
          float* __restrict__ out)
{
    extern __shared__ float sm[];
    const int t = threadIdx.x, lane = t & 31, w = t >> 5;
    const int g = w >> 1, wg = w & 1, tg = t & 63;
    const int m0 = (blockIdx.x >> 1) * 16, n0 = (blockIdx.x & 1) * 64;
    float* As  = sm + g * 16 * LDS_;               // per-group 16 x LDS_
    float* Bs  = sm + 32 * LDS_ + g * 64 * LDS_;   // per-group 64 x LDS_
    float* red = sm + 160 * LDS_;                  // 16 x 66

    u64 acc[8][2];
    #pragma unroll
    for (int i = 0; i < 8; i++) { acc[i][0] = 0ull; acc[i][1] = 0ull; }

    #pragma unroll
    for (int z = 0; z < 2; z++) {
        const int k0 = (g * 2 + z) * 128;
        #pragma unroll
        for (int i = 0; i < 8; i++) {
            int idx = tg + i * 64; int r = idx >> 5, c4 = idx & 31;
            *(float4*)(As + r * LDS_ + c4 * 4) =
                *(const float4*)(g_r + (size_t)(m0 + r) * 512 + k0 + c4 * 4);
        }
        // transpose op_W[k0+kk][n0..n0+64) -> Bs[n][kk]; kk owned per-thread: STS conflict-free
        #pragma unroll
        for (int h = 0; h < 2; h++) {
            int kk = tg + h * 64;
            #pragma unroll
            for (int p4 = 0; p4 < 16; p4++) {
                float4 v = *(const float4*)(opW + (size_t)(k0 + kk) * 128 + n0 + p4 * 4);
                Bs[(p4 * 4 + 0) * LDS_ + kk] = v.x;
                Bs[(p4 * 4 + 1) * LDS_ + kk] = v.y;
                Bs[(p4 * 4 + 2) * LDS_ + kk] = v.z;
                Bs[(p4 * 4 + 3) * LDS_ + kk] = v.w;
            }
        }
        __syncthreads();
        wtile(As, Bs, wg * 8, lane, acc);
        __syncthreads();
    }

    if (g == 1) {
        #pragma unroll
        for (int i = 0; i < 8; i++)
            #pragma unroll
            for (int j = 0; j < 2; j++)
                red[(wg * 8 + i) * 66 + lane + 32 * j] = f2lo(acc[i][j]) + f2hi(acc[i][j]);
    }
    __syncthreads();
    if (g == 0) {
        #pragma unroll
        for (int i = 0; i < 8; i++) {
            int m = m0 + wg * 8 + i;
            #pragma unroll
            for (int j = 0; j < 2; j++) {
                int n = n0 + lane + 32 * j;
                float v = f2lo(acc[i][j]) + f2hi(acc[i][j])
                        + red[(wg * 8 + i) * 66 + lane + 32 * j] + opb[n];
                float xv = x[(size_t)m * 128 + n];
                float mv = mask[(size_t)m * 128 + n];
                out[(size_t)m * 128 + n] = xv * (1.0f - mv) + v * mv;
            }
        }
    }
}

extern "C" void kernel_launch(void* const* d_in, const int* in_sizes, int n_in,
                              void* d_out, int out_size)
{
    const float* x    = (const float*)d_in[0];
    const float* mask = (const float*)d_in[1];
    const float* emb  = (const float*)d_in[2];
    const float* gatW = (const float*)d_in[3];
    // d_in[4] = gat_a: provably unused (softmax over constant logits -> adj/k; rows sum to 1)
    const float* fpW  = (const float*)d_in[5];
    const float* fpb  = (const float*)d_in[6];
    const float* opW  = (const float*)d_in[7];
    const float* opb  = (const float*)d_in[8];
    const int*   kp   = (const int*)d_in[9];
    float* out = (float*)d_out;

    const int SM1 = (128 * LDS_ + 128 + 256) * 4;   // 69120 B (adj role is max)
    const int SM2 = 96 * LDS_ * 4;                  // 50688 B
    const int SM3 = (160 * LDS_ + 16 * 66) * 4;     // 88704 B
    cudaFuncSetAttribute(k1_kernel, cudaFuncAttributeMaxDynamicSharedMemorySize, SM1);
    cudaFuncSetAttribute(k2_kernel, cudaFuncAttributeMaxDynamicSharedMemorySize, SM2);
    cudaFuncSetAttribute(k3_kernel, cudaFuncAttributeMaxDynamicSharedMemorySize, SM3);

    k1_kernel<<<96, 128, SM1>>>(emb, x, fpW, fpb, kp, out);
    k2_kernel<<<128, 128, SM2>>>(gatW);
    k3_kernel<<<64, 128, SM3>>>(x, mask, opW, opb, out);
}

// round 4
// speedup vs baseline: 1.9023x; 1.1857x over previous
#include <cuda_runtime.h>

#define NBLK 128
#define NTHR 128
#define LDS_ 132   // padded smem row stride (floats): 528B, 16B-aligned, conflict-free float4
typedef unsigned long long u64;

// Scratch (allocation-free rule: __device__ globals)
__device__ float g_h0[512 * 128];    // x @ fp_W + fp_b
__device__ float g_r[512 * 512];     // relu(h0 @ gat_W^T)
__device__ float g_opWt[128 * 512];  // op_W transposed: [n][k]
__device__ unsigned g_cnt = 0;       // barrier arrivals (returns to 0 every launch)
__device__ unsigned g_gen = 0;       // barrier generation (monotonic across launches — fine)

__device__ __forceinline__ void grid_barrier()
{
    __threadfence();
    __syncthreads();
    if (threadIdx.x == 0) {
        unsigned gen = *(volatile unsigned*)&g_gen;   // read BEFORE arriving
        unsigned t = atomicAdd(&g_cnt, 1u);
        if (t == NBLK - 1) {
            g_cnt = 0;
            __threadfence();
            atomicAdd(&g_gen, 1u);                    // release
        } else {
            while (*(volatile unsigned*)&g_gen == gen) { }
        }
    }
    __syncthreads();
}

__device__ __forceinline__ u64 ffma2(u64 a, u64 b, u64 c) {
    u64 d;
    asm("fma.rn.f32x2 %0, %1, %2, %3;" : "=l"(d) : "l"(a), "l"(b), "l"(c));
    return d;
}
__device__ __forceinline__ float f2lo(u64 v) { return __uint_as_float((unsigned)v); }
__device__ __forceinline__ float f2hi(u64 v) { return __uint_as_float((unsigned)(v >> 32)); }

// Warp tile: 8 m-rows (As, broadcast reads) x 64 n (lane + 32j, strided conflict-free)
// over one K=128 chunk. acc packs (even k, odd k) in f32x2.
__device__ __forceinline__ void wtile8(const float* __restrict__ As,
                                       const float* __restrict__ Bs,
                                       int lane, u64 acc[8][2])
{
    #pragma unroll 4
    for (int k4 = 0; k4 < 32; k4++) {
        ulonglong2 b0 = *(const ulonglong2*)(Bs + (size_t)lane        * LDS_ + k4 * 4);
        ulonglong2 b1 = *(const ulonglong2*)(Bs + (size_t)(lane + 32) * LDS_ + k4 * 4);
        #pragma unroll
        for (int i = 0; i < 8; i++) {
            ulonglong2 a = *(const ulonglong2*)(As + (size_t)i * LDS_ + k4 * 4);
            acc[i][0] = ffma2(a.x, b0.x, acc[i][0]);
            acc[i][0] = ffma2(a.y, b0.y, acc[i][0]);
            acc[i][1] = ffma2(a.x, b1.x, acc[i][1]);
            acc[i][1] = ffma2(a.y, b1.y, acc[i][1]);
        }
    }
}

__global__ void __launch_bounds__(NTHR, 1)
fused_kernel(const float* __restrict__ x,   const float* __restrict__ mask,
             const float* __restrict__ emb, const float* __restrict__ gatW,
             const float* __restrict__ fpW, const float* __restrict__ fpb,
             const float* __restrict__ opW, const float* __restrict__ opb,
             const int*   __restrict__ kp,  float* __restrict__ out)
{
    extern __shared__ float sm[];
    const int blk = blockIdx.x, t = threadIdx.x, lane = t & 31, w = t >> 5;

    // ═ Phase 0: adj (0..63) ∥ h0 GEMM (64..95) ∥ opW transpose (96..127) ═══
    if (blk < 64) {
        // cosine-sim top-k adjacency rows 2blk, 2blk+1 (lower index wins ties)
        float* es    = sm;                 // 128 x LDS_
        float* s_n2  = sm + 128 * LDS_;    // 128
        float* s_sim = s_n2 + 128;         // 2 x 128 (16B aligned)
        #pragma unroll
        for (int i = 0; i < 32; i++) {
            int idx = t + i * 128; int r = idx >> 5, c4 = idx & 31;
            *(float4*)(es + r * LDS_ + c4 * 4) =
                *(const float4*)(emb + (size_t)r * 128 + c4 * 4);
        }
        __syncthreads();
        const int i0 = blk * 2, i1 = i0 + 1, j = t;
        const float* e0 = es + i0 * LDS_;
        const float* e1 = es + i1 * LDS_;
        const float* ej = es + j * LDS_;
        float d0 = 0.f, d1 = 0.f, nj = 0.f;
        #pragma unroll 8
        for (int f4 = 0; f4 < 32; f4++) {
            float4 b  = *(const float4*)(ej + f4 * 4);
            float4 a0 = *(const float4*)(e0 + f4 * 4);
            float4 a1 = *(const float4*)(e1 + f4 * 4);
            d0 += a0.x * b.x + a0.y * b.y + a0.z * b.z + a0.w * b.w;
            d1 += a1.x * b.x + a1.y * b.y + a1.z * b.z + a1.w * b.w;
            nj += b.x * b.x + b.y * b.y + b.z * b.z + b.w * b.w;
        }
        s_n2[j] = nj;
        __syncthreads();
        float sj = sqrtf(nj);
        float r0 = d0 / (sqrtf(s_n2[i0]) * sj);
        float r1 = d1 / (sqrtf(s_n2[i1]) * sj);
        s_sim[j] = r0; s_sim[128 + j] = r1;
        __syncthreads();
        const float4* S0 = (const float4*)s_sim;
        const float4* S1 = (const float4*)(s_sim + 128);
        int c0 = 0, c1 = 0;
        #pragma unroll 8
        for (int q = 0; q < 32; q++) {
            float4 a = S0[q], b = S1[q];
            int base = q * 4;
            c0 += (a.x > r0) || (a.x == r0 && base + 0 < j);
            c0 += (a.y > r0) || (a.y == r0 && base + 1 < j);
            c0 += (a.z > r0) || (a.z == r0 && base + 2 < j);
            c0 += (a.w > r0) || (a.w == r0 && base + 3 < j);
            c1 += (b.x > r1) || (b.x == r1 && base + 0 < j);
            c1 += (b.y > r1) || (b.y == r1 && base + 1 < j);
            c1 += (b.z > r1) || (b.z == r1 && base + 2 < j);
            c1 += (b.w > r1) || (b.w == r1 && base + 3 < j);
        }
        int k = kp[0];
        out[65536 + i0 * 128 + j] = (c0 < k) ? 1.0f : 0.0f;
        out[65536 + i1 * 128 + j] = (c1 < k) ? 1.0f : 0.0f;
    } else if (blk < 96) {
        // h0 tile [32 x 64]: h0 = x @ fp_W + fp_b, K=128
        int tt = blk - 64;
        int m0 = (tt >> 1) * 32, n0 = (tt & 1) * 64;
        float* As = sm;               // 32 x LDS_
        float* Bs = sm + 32 * LDS_;   // 64 x LDS_  (row = n_local, col = k)
        #pragma unroll
        for (int i = 0; i < 8; i++) {
            int idx = t + i * 128; int r = idx >> 5, c4 = idx & 31;
            *(float4*)(As + r * LDS_ + c4 * 4) =
                *(const float4*)(x + (size_t)(m0 + r) * 128 + c4 * 4);
        }
        // transpose fp_W cols [n0, n0+64): thread t owns k-row t -> conflict-free STS
        #pragma unroll
        for (int p4 = 0; p4 < 16; p4++) {
            float4 v = *(const float4*)(fpW + (size_t)t * 128 + n0 + p4 * 4);
            Bs[(p4 * 4 + 0) * LDS_ + t] = v.x;
            Bs[(p4 * 4 + 1) * LDS_ + t] = v.y;
            Bs[(p4 * 4 + 2) * LDS_ + t] = v.z;
            Bs[(p4 * 4 + 3) * LDS_ + t] = v.w;
        }
        __syncthreads();
        u64 acc[8][2];
        #pragma unroll
        for (int i = 0; i < 8; i++) { acc[i][0] = 0ull; acc[i][1] = 0ull; }
        wtile8(As + (size_t)(w * 8) * LDS_, Bs, lane, acc);
        #pragma unroll
        for (int i = 0; i < 8; i++) {
            int m = m0 + w * 8 + i;
            #pragma unroll
            for (int j = 0; j < 2; j++) {
                int n = n0 + lane + 32 * j;
                g_h0[(size_t)m * 128 + n] = f2lo(acc[i][j]) + f2hi(acc[i][j]) + fpb[n];
            }
        }
    } else {
        // opW transpose: block handles k-slice [b*16, b*16+16), thread t = column n
        int k0 = (blk - 96) * 16;
        float v[16];
        #pragma unroll
        for (int kk = 0; kk < 16; kk++)
            v[kk] = opW[(size_t)(k0 + kk) * 128 + t];
        #pragma unroll
        for (int q = 0; q < 4; q++)
            *(float4*)(g_opWt + (size_t)t * 512 + k0 + q * 4) =
                make_float4(v[q * 4], v[q * 4 + 1], v[q * 4 + 2], v[q * 4 + 3]);
    }
    grid_barrier();

    // ═ Phase 1: r = relu(h0 @ gat_W^T), 512x512 — 128 tiles of [32 x 64] ════
    {
        float* As = sm;               // 32 x LDS_
        float* Bs = sm + 32 * LDS_;   // 64 x LDS_
        const int m0 = (blk >> 3) * 32, c0 = (blk & 7) * 64;
        #pragma unroll
        for (int i = 0; i < 8; i++) {
            int idx = t + i * 128; int r = idx >> 5, c4 = idx & 31;
            *(float4*)(As + r * LDS_ + c4 * 4) =
                *(const float4*)(g_h0 + (size_t)(m0 + r) * 128 + c4 * 4);
        }
        #pragma unroll
        for (int i = 0; i < 16; i++) {
            int idx = t + i * 128; int r = idx >> 5, c4 = idx & 31;
            *(float4*)(Bs + r * LDS_ + c4 * 4) =
                *(const float4*)(gatW + (size_t)(c0 + r) * 128 + c4 * 4);
        }
        __syncthreads();
        u64 acc[8][2];
        #pragma unroll
        for (int i = 0; i < 8; i++) { acc[i][0] = 0ull; acc[i][1] = 0ull; }
        wtile8(As + (size_t)(w * 8) * LDS_, Bs, lane, acc);
        #pragma unroll
        for (int i = 0; i < 8; i++) {
            int m = m0 + w * 8 + i;
            #pragma unroll
            for (int j = 0; j < 2; j++) {
                int c = c0 + lane + 32 * j;
                g_r[(size_t)m * 512 + c] = fmaxf(f2lo(acc[i][j]) + f2hi(acc[i][j]), 0.0f);
            }
        }
    }
    grid_barrier();

    // ═ Phase 2: out = x(1-mask) + (r @ op_W + op_b)·mask — tiles [8m x 64n],
    //   4-way K-split across warps (warp w: k in [w*128, w*128+128)) ═════════
    {
        float* As = sm;               // [4 chunks][8 rows][LDS_]
        float* Bs = sm + 32 * LDS_;   // [4 warps][64 rows][LDS_]
        float* red = sm;              // reuse As region after sync: 4*512 floats
        const int m0 = (blk >> 1) * 8, n0 = (blk & 1) * 64;

        #pragma unroll
        for (int i = 0; i < 8; i++) {
            int idx = t + i * 128;          // over (m 0..7) x (kq 0..127)
            int m = idx >> 7, kq = idx & 127;
            int c = kq >> 5, kl = kq & 31;
            *(float4*)(As + (size_t)(c * 8 + m) * LDS_ + kl * 4) =
                *(const float4*)(g_r + (size_t)(m0 + m) * 512 + kq * 4);
        }
        #pragma unroll
        for (int q = 0; q < 2; q++) {
            #pragma unroll
            for (int h = 0; h < 32; h++) {
                int idx = lane + (q * 32 + h) * 32;  // over (row 0..63) x (k4 0..31)
                int row = idx >> 5, k4 = idx & 31;
                *(float4*)(Bs + (size_t)(w * 64 + row) * LDS_ + k4 * 4) =
                    *(const float4*)(g_opWt + (size_t)(n0 + row) * 512 + w * 128 + k4 * 4);
            }
        }
        __syncthreads();
        u64 acc[8][2];
        #pragma unroll
        for (int i = 0; i < 8; i++) { acc[i][0] = 0ull; acc[i][1] = 0ull; }
        wtile8(As + (size_t)(w * 8) * LDS_, Bs + (size_t)(w * 64) * LDS_, lane, acc);
        __syncthreads();
        #pragma unroll
        for (int i = 0; i < 8; i++)
            #pragma unroll
            for (int j = 0; j < 2; j++)
                red[w * 512 + i * 64 + lane + 32 * j] = f2lo(acc[i][j]) + f2hi(acc[i][j]);
        __syncthreads();
        #pragma unroll
        for (int q = 0; q < 4; q++) {
            int o = t + q * 128;            // 0..511
            int m = o >> 6, n = o & 63;
            float v = red[o] + red[512 + o] + red[1024 + o] + red[1536 + o] + opb[n0 + n];
            size_t gi = (size_t)(m0 + m) * 128 + n0 + n;
            float xv = x[gi], mv = mask[gi];
            out[gi] = xv * (1.0f - mv) + v * mv;
        }
    }
}

extern "C" void kernel_launch(void* const* d_in, const int* in_sizes, int n_in,
                              void* d_out, int out_size)
{
    const float* x    = (const float*)d_in[0];
    const float* mask = (const float*)d_in[1];
    const float* emb  = (const float*)d_in[2];
    const float* gatW = (const float*)d_in[3];
    // d_in[4] = gat_a: provably unused (softmax over constant logits -> adj/k; rows sum to 1)
    const float* fpW  = (const float*)d_in[5];
    const float* fpb  = (const float*)d_in[6];
    const float* opW  = (const float*)d_in[7];
    const float* opb  = (const float*)d_in[8];
    const int*   kp   = (const int*)d_in[9];
    float* out = (float*)d_out;

    // max over phases: phase2 = (32 + 256) * LDS_ floats = 152064 B
    const int SMEM = (32 + 256) * LDS_ * 4;
    cudaFuncSetAttribute(fused_kernel, cudaFuncAttributeMaxDynamicSharedMemorySize, SMEM);
    fused_kernel<<<NBLK, NTHR, SMEM>>>(x, mask, emb, gatW, fpW, fpb, opW, opb, kp, out);
}